// round 17
// baseline (speedup 1.0000x reference)
#include <cuda_runtime.h>
#include <cuda_bf16.h>
#include <cstdint>

#define HW   1024
#define CD   128
#define EPSF 1e-8f
#define STAGE_B 32768   // kc=32 stage: A_hi 8K | A_lo 8K | B_hi 8K | B_lo 8K

// Normalized features, bf16 hi/lo split, pixel-major:
// g_feat[view][p][0..127]=hi, [128..255]=lo   (512 B per pixel row)
__device__ __nv_bfloat16 g_feat[32 * HW * 256];

// ---------------------------------------------------------------------------
__device__ __forceinline__ uint32_t smem_u32(const void* p) {
    uint32_t a;
    asm("{ .reg .u64 t; cvta.to.shared.u64 t, %1; cvt.u32.u64 %0, t; }" : "=r"(a) : "l"(p));
    return a;
}

#define CP_ASYNC(s, g) \
    asm volatile("cp.async.cg.shared.global [%0], [%1], 16;" :: "r"(s), "l"(g))
#define CP_COMMIT() asm volatile("cp.async.commit_group;" ::: "memory")
#define CP_WAIT0()  asm volatile("cp.async.wait_group 0;" ::: "memory")

#define LDSM4(r, a) \
    asm volatile("ldmatrix.sync.aligned.m8n8.x4.shared.b16 {%0,%1,%2,%3}, [%4];" \
        : "=r"((r)[0]), "=r"((r)[1]), "=r"((r)[2]), "=r"((r)[3]) : "r"(a))

#define MMA(d, a, b0v, b1v)                                                  \
    asm volatile(                                                            \
        "mma.sync.aligned.m16n8k16.row.col.f32.bf16.bf16.f32 "               \
        "{%0,%1,%2,%3}, {%4,%5,%6,%7}, {%8,%9}, {%0,%1,%2,%3};\n"            \
        : "+f"((d)[0]), "+f"((d)[1]), "+f"((d)[2]), "+f"((d)[3])             \
        : "r"((a)[0]), "r"((a)[1]), "r"((a)[2]), "r"((a)[3]),                \
          "r"(b0v), "r"(b1v))

// ---------------------------------------------------------------------------
// Kernel 1 (v2): L2-normalize per pixel + bf16 hi/lo split, pixel-major out.
// ---------------------------------------------------------------------------
__global__ __launch_bounds__(256) void norm_split_kernel2(const float* __restrict__ x) {
    int t = blockIdx.x * 256 + threadIdx.x;      // 0..131071
    int gp = t >> 2;                             // pixel over all views
    int qt = t & 3;                              // channel quarter 0..3
    int view = gp >> 10, p = gp & 1023;

    const float* xp = x + (size_t)view * (CD * HW) + (size_t)(qt * 32) * HW + p;

    float v[32];
    float s = 0.f;
#pragma unroll
    for (int c = 0; c < 32; ++c) {
        v[c] = xp[c << 10];
        s += v[c] * v[c];
    }
    s += __shfl_xor_sync(0xFFFFFFFFu, s, 1);
    s += __shfl_xor_sync(0xFFFFFFFFu, s, 2);
    float inv = 1.f / (sqrtf(s) + EPSF);

    __nv_bfloat16* row = g_feat + (size_t)gp * 256 + qt * 32;
    ushort hi[32], lo[32];
#pragma unroll
    for (int c = 0; c < 32; ++c) {
        float f = v[c] * inv;
        __nv_bfloat16 h = __float2bfloat16(f);
        hi[c] = __bfloat16_as_ushort(h);
        lo[c] = __bfloat16_as_ushort(__float2bfloat16(f - __bfloat162float(h)));
    }
#pragma unroll
    for (int c8 = 0; c8 < 4; ++c8) {
        uint4 vh, vl;
        vh.x = (uint32_t)hi[c8*8+0] | ((uint32_t)hi[c8*8+1] << 16);
        vh.y = (uint32_t)hi[c8*8+2] | ((uint32_t)hi[c8*8+3] << 16);
        vh.z = (uint32_t)hi[c8*8+4] | ((uint32_t)hi[c8*8+5] << 16);
        vh.w = (uint32_t)hi[c8*8+6] | ((uint32_t)hi[c8*8+7] << 16);
        vl.x = (uint32_t)lo[c8*8+0] | ((uint32_t)lo[c8*8+1] << 16);
        vl.y = (uint32_t)lo[c8*8+2] | ((uint32_t)lo[c8*8+3] << 16);
        vl.z = (uint32_t)lo[c8*8+4] | ((uint32_t)lo[c8*8+5] << 16);
        vl.w = (uint32_t)lo[c8*8+6] | ((uint32_t)lo[c8*8+7] << 16);
        *(uint4*)(row + c8 * 8)       = vh;
        *(uint4*)(row + 128 + c8 * 8) = vl;
    }
}

// ---------------------------------------------------------------------------
// Kernel 2: HMMA GEMM over 48 unique view pairs; CTA tile 128x128 with only
// 4 warps (2x2 grid, warp tile 64x64 -> 85B smem per MMA vs 128 before).
// kc=32, 2-stage cp.async, one sync per chunk. 128 thr/CTA, 2 CTAs/SM
// (=> 256 regs/thread available; acc 128 + frags 64 fits, no spill).
// Direct stores to out[idx1]; transposed twin to out[idx2] via per-warp
// swizzled smem (2 rounds of 32 n-rows). smem 64KB.
// ---------------------------------------------------------------------------
__constant__ int c_pi[6] = {0, 0, 0, 1, 1, 2};
__constant__ int c_pj[6] = {1, 2, 3, 2, 3, 3};

__global__ __launch_bounds__(128, 2) void corr_gemm11(float* __restrict__ out) {
    extern __shared__ char smem[];
    uint32_t sb = smem_u32(smem);
    const int tid = threadIdx.x;
    const int w = tid >> 5, l = tid & 31;
    const int wm = w >> 1, wn = w & 1;          // warp grid 2x2
    const int lo16 = l & 15, hi2 = l >> 4;
    const int g = l >> 2, tg = l & 3;

    const int q0 = blockIdx.x * 128;
    const int p0 = blockIdx.y * 128;
    const int z  = blockIdx.z;                  // 0..47
    const int b  = z / 6, u = z % 6;
    const int i  = c_pi[u], j = c_pj[u];
    const int idx1 = b * 12 + i * 3 + (j - 1);
    const int idx2 = b * 12 + j * 3 + i;

    const char* Af = (const char*)g_feat + (size_t)(b * 4 + j) * HW * 512 + (size_t)p0 * 512;
    const char* Bf = (const char*)g_feat + (size_t)(b * 4 + i) * HW * 512 + (size_t)q0 * 512;

    float acc[4][8][4];
#pragma unroll
    for (int mt = 0; mt < 4; ++mt)
#pragma unroll
        for (int nt = 0; nt < 8; ++nt)
#pragma unroll
            for (int e = 0; e < 4; ++e) acc[mt][nt][e] = 0.f;

    // ---- stage loader: 2048 16B chunks (A 1024 + B 1024), 16 per thread ----
    auto load_stage = [&](int kc) {
        uint32_t sbase = sb + (uint32_t)(kc & 1) * STAGE_B;
        const char* Ak = Af + kc * 64;
        const char* Bk = Bf + kc * 64;
#pragma unroll
        for (int it = 0; it < 8; ++it) {
            int c = it * 128 + tid;             // 0..1023
            int m = c >> 3, half = (c >> 2) & 1, ch = c & 3;
            uint32_t soff = half * 8192u
                          + (uint32_t)((m * 4 + (ch ^ ((m >> 1) & 3))) << 4);
            size_t goff = (size_t)m * 512 + half * 256 + ch * 16;
            CP_ASYNC(sbase + soff,          Ak + goff);
            CP_ASYNC(sbase + 16384u + soff, Bk + goff);
        }
    };

    load_stage(0);
    CP_COMMIT();

    for (int kc = 0; kc < 4; ++kc) {
        CP_WAIT0();
        __syncthreads();
        if (kc < 3) { load_stage(kc + 1); CP_COMMIT(); }

        uint32_t st = sb + (uint32_t)(kc & 1) * STAGE_B;
#pragma unroll
        for (int ks = 0; ks < 2; ++ks) {
            const int ch = ks * 2 + hi2;        // lane's 16B chunk (0..3)

            uint32_t ah[4][4], al[4][4], bh[4][4], bl[4][4];
            uint32_t swa[4], swb[4];
#pragma unroll
            for (int np = 0; np < 4; ++np) {    // B hi: 64 cols
                int n = wn * 64 + np * 16 + lo16;
                swb[np] = (uint32_t)((n * 4 + (ch ^ ((n >> 1) & 3))) << 4);
                LDSM4(bh[np], st + 16384 + swb[np]);
            }
#pragma unroll
            for (int mt = 0; mt < 4; ++mt) {    // A hi: 64 rows
                int m = wm * 64 + mt * 16 + lo16;
                swa[mt] = (uint32_t)((m * 4 + (ch ^ ((m >> 1) & 3))) << 4);
                LDSM4(ah[mt], st + swa[mt]);
            }
            // hh
#pragma unroll
            for (int mt = 0; mt < 4; ++mt)
#pragma unroll
                for (int np = 0; np < 4; ++np)
#pragma unroll
                    for (int s2 = 0; s2 < 2; ++s2)
                        MMA(acc[mt][np * 2 + s2], ah[mt], bh[np][s2], bh[np][2 + s2]);
            // A lo
#pragma unroll
            for (int mt = 0; mt < 4; ++mt)
                LDSM4(al[mt], st + 8192 + swa[mt]);
            // lh
#pragma unroll
            for (int mt = 0; mt < 4; ++mt)
#pragma unroll
                for (int np = 0; np < 4; ++np)
#pragma unroll
                    for (int s2 = 0; s2 < 2; ++s2)
                        MMA(acc[mt][np * 2 + s2], al[mt], bh[np][s2], bh[np][2 + s2]);
            // B lo
#pragma unroll
            for (int np = 0; np < 4; ++np)
                LDSM4(bl[np], st + 24576 + swb[np]);
            // hl
#pragma unroll
            for (int mt = 0; mt < 4; ++mt)
#pragma unroll
                for (int np = 0; np < 4; ++np)
#pragma unroll
                    for (int s2 = 0; s2 < 2; ++s2)
                        MMA(acc[mt][np * 2 + s2], ah[mt], bl[np][s2], bl[np][2 + s2]);
        }
    }

    // ---- epilogue 1: direct fp32 float2 stores to out[idx1] ----
    {
        float* op = out + (size_t)idx1 * (HW * HW);
#pragma unroll
        for (int mt = 0; mt < 4; ++mt) {
#pragma unroll
            for (int nt = 0; nt < 8; ++nt) {
                int row = p0 + wm * 64 + mt * 16 + g;
                int col = q0 + wn * 64 + nt * 8 + tg * 2;
                *(float2*)&op[(size_t)row * HW + col] =
                    make_float2(acc[mt][nt][0], acc[mt][nt][1]);
                *(float2*)&op[(size_t)(row + 8) * HW + col] =
                    make_float2(acc[mt][nt][2], acc[mt][nt][3]);
            }
        }
    }

    // ---- epilogue 2: transposed tile to out[idx2], 2 rounds of 32 n-rows --
    __syncthreads();                // tw aliases the dead stage buffers
    {
        float* tw = (float*)smem + w * 2048;   // per-warp 8KB: 32 n x 64 m
        float* op = out + (size_t)idx2 * (HW * HW);
#pragma unroll
        for (int r = 0; r < 2; ++r) {
#pragma unroll
            for (int nt = 0; nt < 4; ++nt)
#pragma unroll
                for (int mt = 0; mt < 4; ++mt)
#pragma unroll
                    for (int e = 0; e < 4; ++e) {
                        int n = nt * 8 + tg * 2 + (e & 1);           // 0..31
                        int m = mt * 16 + g + 8 * (e >> 1);          // 0..63
                        tw[n * 64 + (m ^ ((n & 6) << 2))] = acc[mt][r * 4 + nt][e];
                    }
            __syncwarp();
            const float2* tw2 = (const float2*)tw;
#pragma unroll
            for (int n = 0; n < 32; ++n) {
                float2 v = tw2[n * 32 + (l ^ ((n & 6) << 1))];   // (G[n][2l], G[n][2l+1])
                *(float2*)&op[(size_t)(q0 + wn * 64 + r * 32 + n) * HW
                              + p0 + wm * 64 + 2 * l] = v;
            }
            __syncwarp();
        }
    }
}

// ---------------------------------------------------------------------------
extern "C" void kernel_launch(void* const* d_in, const int* in_sizes, int n_in,
                              void* d_out, int out_size) {
    const float* x = (const float*)d_in[0];
    float* out = (float*)d_out;

    norm_split_kernel2<<<512, 256>>>(x);

    int smem_sz = 2 * STAGE_B;   // 64 KB
    cudaFuncSetAttribute(corr_gemm11, cudaFuncAttributeMaxDynamicSharedMemorySize, smem_sz);
    dim3 grid(8, 8, 48);
    corr_gemm11<<<grid, 128, smem_sz>>>(out);
}